// round 5
// baseline (speedup 1.0000x reference)
#include <cuda_runtime.h>
#include <cuda_fp16.h>
#include <mma.h>
#include <cstdint>

using namespace nvcuda;

// out[b,s,f] = scale * x[b,s,:] @ W, W = kernel ? +1 : -1
// GEMM: M=16384, K=1024, N=1024. fp16 wmma (HMMA), fp32 accum.
// fp32->fp16 conversion of x is FUSED into the GEMM producer path
// (LDG fp32 early, cvt+STS late, latency hidden under mma work).

#define M_TOTAL 16384
#define N_TOTAL 1024
#define K_TOTAL 1024

#define BM 128
#define BN 128
#define BK 32
#define STAGES 4
#define NCHUNK (K_TOTAL / BK)      // 32
#define ASTRIDE 80                 // bytes per smem row: 64B data + 16B pad
#define A_SM_BYTES (BM * ASTRIDE)  // 10240
#define B_SM_BYTES (BN * ASTRIDE)  // 10240
#define STAGE_BYTES (A_SM_BYTES + B_SM_BYTES)   // 20480
#define SMEM_TOTAL (STAGES * STAGE_BYTES)       // 81920

__device__ __half g_b[(size_t)N_TOTAL * K_TOTAL];    // 2 MB, [n][k] = +/-1

// ---------------- helpers ----------------
__device__ __forceinline__ uint32_t smem_u32(const void* p) {
    uint32_t a;
    asm("{ .reg .u64 t; cvta.to.shared.u64 t, %1; cvt.u32.u64 %0, t; }" : "=r"(a) : "l"(p));
    return a;
}
__device__ __forceinline__ void cp_async16(uint32_t dst, const void* src) {
    asm volatile("cp.async.cg.shared.global [%0], [%1], 16;" :: "r"(dst), "l"(src) : "memory");
}
__device__ __forceinline__ uint4 cvt8(float4 f0, float4 f1) {
    __half2 h[4];
    h[0] = __floats2half2_rn(f0.x, f0.y);
    h[1] = __floats2half2_rn(f0.z, f0.w);
    h[2] = __floats2half2_rn(f1.x, f1.y);
    h[3] = __floats2half2_rn(f1.z, f1.w);
    return *(uint4*)h;
}

// ---------------- weight prep: dtype-width detect + transpose ----------------
// Detection (per block, redundant but parallel): scan first 1024 words.
// Word-packed bool (int32 0/1 or f32 0/1.0): words in {0,1,0x3F800000}.
// Halfword-packed (bf16/f16 0/1): halfwords in {0,1,0x3F80,0x3C00}. Else bytes.
__global__ void transpose_b_kernel(const void* __restrict__ kern) {
    __shared__ unsigned char tile[32][33];
    __shared__ int notw, noth;
    int tx = threadIdx.x, ty = threadIdx.y;
    int t = ty * 32 + tx;
    if (t == 0) { notw = 0; noth = 0; }
    __syncthreads();
    const uint32_t* kw = (const uint32_t*)kern;
    for (int i = t; i < 1024; i += 256) {
        uint32_t w = kw[i];
        if (!(w == 0u || w == 1u || w == 0x3F800000u)) notw = 1;
        uint32_t h0 = w & 0xFFFFu, h1 = w >> 16;
        if (!((h0 == 0u || h0 == 1u || h0 == 0x3F80u || h0 == 0x3C00u) &&
              (h1 == 0u || h1 == 1u || h1 == 0x3F80u || h1 == 0x3C00u))) noth = 1;
    }
    __syncthreads();
    int width = (!notw) ? 4 : ((!noth) ? 2 : 1);

    int n0 = blockIdx.x * 32, k0 = blockIdx.y * 32;
    #pragma unroll
    for (int r = ty; r < 32; r += 8) {
        size_t idx = (size_t)(k0 + r) * N_TOTAL + n0 + tx;
        bool v = (width == 4) ? (((const uint32_t*)kern)[idx] != 0u)
               : (width == 2) ? (((const uint16_t*)kern)[idx] != 0u)
                              : (((const uint8_t*)kern)[idx] != 0u);
        tile[r][tx] = v ? 1 : 0;
    }
    __syncthreads();
    const __half pos = __float2half(1.0f), neg = __float2half(-1.0f);
    #pragma unroll
    for (int r = ty; r < 32; r += 8)
        g_b[(size_t)(n0 + r) * K_TOTAL + k0 + tx] = tile[tx][r] ? pos : neg;
}

// ---------------- GEMM (wmma multistage, fused A convert) ----------------
__global__ __launch_bounds__(256, 2)
void gemm_kernel(const float* __restrict__ x, const float* __restrict__ scale_ptr,
                 float* __restrict__ out) {
    extern __shared__ __align__(16) char smem[];
    uint32_t sbase = smem_u32(smem);
    int tid = threadIdx.x;
    int wid = tid >> 5;

    int n0 = blockIdx.x * BN;
    int m0 = blockIdx.y * BM;

    // warp tile: 32(M) x 64(N); warps laid out 4(M) x 2(N)
    int wm = (wid & 3) * 32;
    int wn = (wid >> 2) * 64;

    // per-thread A chunk coords (2 chunks of 16B fp16 = 32B fp32 each)
    int c0 = tid, c1 = tid + 256;
    int r0_ = c0 >> 2, s0_ = c0 & 3;
    int r1_ = c1 >> 2, s1_ = c1 & 3;
    const float* asrc0 = x + (size_t)(m0 + r0_) * K_TOTAL + s0_ * 8;
    const float* asrc1 = x + (size_t)(m0 + r1_) * K_TOTAL + s1_ * 8;
    uint32_t adst0 = r0_ * ASTRIDE + s0_ * 16;
    uint32_t adst1 = r1_ * ASTRIDE + s1_ * 16;

    auto load_b_stage = [&](int kc, int s) {
        uint32_t sB = sbase + s * STAGE_BYTES + A_SM_BYTES;
        #pragma unroll
        for (int i = 0; i < 2; i++) {           // B: 512 x 16B chunks / 256 threads
            int c = tid + i * 256;
            int row = c >> 2, seg = c & 3;
            cp_async16(sB + row * ASTRIDE + seg * 16,
                       &g_b[(size_t)(n0 + row) * K_TOTAL + kc + seg * 8]);
        }
    };

    // ---- prologue: stages 0..2 (A synchronous LDG+cvt+STS, B async) ----
    #pragma unroll
    for (int s = 0; s < STAGES - 1; s++) {
        int kc = s * BK;
        char* sA = smem + s * STAGE_BYTES;
        float4 f0 = *(const float4*)(asrc0 + kc);
        float4 f1 = *(const float4*)(asrc0 + kc + 4);
        *(uint4*)(sA + adst0) = cvt8(f0, f1);
        f0 = *(const float4*)(asrc1 + kc);
        f1 = *(const float4*)(asrc1 + kc + 4);
        *(uint4*)(sA + adst1) = cvt8(f0, f1);
        load_b_stage(kc, s);
        asm volatile("cp.async.commit_group;" ::: "memory");
    }

    wmma::fragment<wmma::accumulator, 16, 16, 16, float> cf[2][4];
    #pragma unroll
    for (int mt = 0; mt < 2; mt++)
        #pragma unroll
        for (int nt = 0; nt < 4; nt++)
            wmma::fill_fragment(cf[mt][nt], 0.0f);

    for (int kc = 0; kc < NCHUNK; kc++) {
        asm volatile("cp.async.wait_group 2;" ::: "memory");
        __syncthreads();

        int pf = kc + STAGES - 1;
        bool do_pf = pf < NCHUNK;
        int pk = pf * BK;
        int ps = pf & (STAGES - 1);

        // issue fp32 A loads for stage pf early (latency hidden under mma ks=0)
        float4 f0a, f1a, f0b, f1b;
        if (do_pf) {
            f0a = *(const float4*)(asrc0 + pk);
            f1a = *(const float4*)(asrc0 + pk + 4);
            f0b = *(const float4*)(asrc1 + pk);
            f1b = *(const float4*)(asrc1 + pk + 4);
            load_b_stage(pk, ps);
        }
        asm volatile("cp.async.commit_group;" ::: "memory");   // empty tail group keeps ids uniform

        int s = kc & (STAGES - 1);
        const char* stA = smem + s * STAGE_BYTES;
        const char* stB = stA + A_SM_BYTES;

        #pragma unroll
        for (int ks = 0; ks < 2; ks++) {       // two k16 steps per BK=32
            wmma::fragment<wmma::matrix_a, 16, 16, 16, __half, wmma::row_major> af[2];
            #pragma unroll
            for (int mt = 0; mt < 2; mt++)
                wmma::load_matrix_sync(af[mt],
                    (const __half*)(stA + (wm + mt * 16) * ASTRIDE + ks * 32), 40);
            // B fragments in pairs to cap register liveness
            #pragma unroll
            for (int np = 0; np < 2; np++) {
                wmma::fragment<wmma::matrix_b, 16, 16, 16, __half, wmma::col_major> bf[2];
                #pragma unroll
                for (int j = 0; j < 2; j++)
                    wmma::load_matrix_sync(bf[j],
                        (const __half*)(stB + (wn + (np * 2 + j) * 16) * ASTRIDE + ks * 32), 40);
                #pragma unroll
                for (int mt = 0; mt < 2; mt++)
                    #pragma unroll
                    for (int j = 0; j < 2; j++)
                        wmma::mma_sync(cf[mt][np * 2 + j], af[mt], bf[j], cf[mt][np * 2 + j]);
            }
            // after ks=0 mma block: convert + STS the prefetched A (frees fp32 regs)
            if (ks == 0 && do_pf) {
                char* dA = smem + ps * STAGE_BYTES;
                *(uint4*)(dA + adst0) = cvt8(f0a, f1a);
                *(uint4*)(dA + adst1) = cvt8(f0b, f1b);
            }
        }
    }

    // ---- epilogue: scale in-fragment, store straight to gmem ----
    float sc = *scale_ptr;
    #pragma unroll
    for (int mt = 0; mt < 2; mt++) {
        #pragma unroll
        for (int nt = 0; nt < 4; nt++) {
            #pragma unroll
            for (int e = 0; e < cf[mt][nt].num_elements; e++)
                cf[mt][nt].x[e] *= sc;
            wmma::store_matrix_sync(
                out + (size_t)(m0 + wm + mt * 16) * N_TOTAL + (n0 + wn + nt * 16),
                cf[mt][nt], N_TOTAL, wmma::mem_row_major);
        }
    }
}

// ---------------- launch ----------------
extern "C" void kernel_launch(void* const* d_in, const int* in_sizes, int n_in,
                              void* d_out, int out_size) {
    // identify inputs by element count (robust to ordering)
    const float* x = nullptr;
    const void* kern = nullptr;
    const float* scale = nullptr;
    for (int i = 0; i < n_in; i++) {
        if (in_sizes[i] == M_TOTAL * K_TOTAL) x = (const float*)d_in[i];
        else if (in_sizes[i] == K_TOTAL * N_TOTAL) kern = (const void*)d_in[i];
        else if (in_sizes[i] == 1) scale = (const float*)d_in[i];
    }
    float* out = (float*)d_out;

    cudaFuncSetAttribute(gemm_kernel, cudaFuncAttributeMaxDynamicSharedMemorySize, SMEM_TOTAL);

    transpose_b_kernel<<<dim3(N_TOTAL / 32, K_TOTAL / 32), dim3(32, 8)>>>(kern);
    // grid.x = N tiles (adjacent CTAs share the A tile in L2), grid.y = M tiles
    gemm_kernel<<<dim3(N_TOTAL / BN, M_TOTAL / BM), 256, SMEM_TOTAL>>>(x, scale, out);
}

// round 6
// speedup vs baseline: 1.0205x; 1.0205x over previous
#include <cuda_runtime.h>
#include <cuda_fp16.h>
#include <mma.h>
#include <cstdint>

using namespace nvcuda;

// out[b,s,f] = scale * x[b,s,:] @ W, W = kernel ? +1 : -1
// GEMM: M=16384, K=1024, N=1024. fp16 wmma (HMMA), fp32 accum.
// R6: 512-thread CTA, warp tile 32x32 -> low reg pressure so ptxas can
// overlap LDSM (L1 pipe) with HMMA (tensor pipe). Separate convert kernel
// (R5 fusion regressed: it loaded the already-contended L1 path).

#define M_TOTAL 16384
#define N_TOTAL 1024
#define K_TOTAL 1024

#define BM 128
#define BN 128
#define BK 32
#define STAGES 4
#define NCHUNK (K_TOTAL / BK)      // 32
#define ASTRIDE 80                 // bytes per smem row: 64B data + 16B pad
#define A_SM_BYTES (BM * ASTRIDE)  // 10240
#define B_SM_BYTES (BN * ASTRIDE)  // 10240
#define STAGE_BYTES (A_SM_BYTES + B_SM_BYTES)   // 20480
#define SMEM_TOTAL (STAGES * STAGE_BYTES)       // 81920
#define THREADS 512

__device__ __half g_xh[(size_t)M_TOTAL * K_TOTAL];   // 32 MB fp16 activations
__device__ __half g_b[(size_t)N_TOTAL * K_TOTAL];    // 2 MB, [n][k] = +/-1

// ---------------- helpers ----------------
__device__ __forceinline__ uint32_t smem_u32(const void* p) {
    uint32_t a;
    asm("{ .reg .u64 t; cvta.to.shared.u64 t, %1; cvt.u32.u64 %0, t; }" : "=r"(a) : "l"(p));
    return a;
}
__device__ __forceinline__ void cp_async16(uint32_t dst, const void* src) {
    asm volatile("cp.async.cg.shared.global [%0], [%1], 16;" :: "r"(dst), "l"(src) : "memory");
}

// ---------------- prep kernels ----------------
__global__ void convert_x_kernel(const float* __restrict__ x) {
    size_t i = (size_t)blockIdx.x * blockDim.x + threadIdx.x;   // 8 floats per thread
    size_t base = i * 8;
    float4 a = *(const float4*)(x + base);
    float4 b = *(const float4*)(x + base + 4);
    __half2 h[4];
    h[0] = __floats2half2_rn(a.x, a.y);
    h[1] = __floats2half2_rn(a.z, a.w);
    h[2] = __floats2half2_rn(b.x, b.y);
    h[3] = __floats2half2_rn(b.z, b.w);
    *(uint4*)(&g_xh[base]) = *(uint4*)h;
}

// dtype-width detect (per block, redundant; L2-cached) + transpose to [n][k] +/-1
__global__ void transpose_b_kernel(const void* __restrict__ kern) {
    __shared__ unsigned char tile[32][33];
    __shared__ int notw, noth;
    int tx = threadIdx.x, ty = threadIdx.y;
    int t = ty * 32 + tx;
    if (t == 0) { notw = 0; noth = 0; }
    __syncthreads();
    const uint32_t* kw = (const uint32_t*)kern;
    for (int i = t; i < 1024; i += 256) {
        uint32_t w = kw[i];
        if (!(w == 0u || w == 1u || w == 0x3F800000u)) notw = 1;
        uint32_t h0 = w & 0xFFFFu, h1 = w >> 16;
        if (!((h0 == 0u || h0 == 1u || h0 == 0x3F80u || h0 == 0x3C00u) &&
              (h1 == 0u || h1 == 1u || h1 == 0x3F80u || h1 == 0x3C00u))) noth = 1;
    }
    __syncthreads();
    int width = (!notw) ? 4 : ((!noth) ? 2 : 1);

    int n0 = blockIdx.x * 32, k0 = blockIdx.y * 32;
    #pragma unroll
    for (int r = ty; r < 32; r += 8) {
        size_t idx = (size_t)(k0 + r) * N_TOTAL + n0 + tx;
        bool v = (width == 4) ? (((const uint32_t*)kern)[idx] != 0u)
               : (width == 2) ? (((const uint16_t*)kern)[idx] != 0u)
                              : (((const uint8_t*)kern)[idx] != 0u);
        tile[r][tx] = v ? 1 : 0;
    }
    __syncthreads();
    const __half pos = __float2half(1.0f), neg = __float2half(-1.0f);
    #pragma unroll
    for (int r = ty; r < 32; r += 8)
        g_b[(size_t)(n0 + r) * K_TOTAL + k0 + tx] = tile[tx][r] ? pos : neg;
}

// ---------------- GEMM (wmma multistage, 512 threads, 32x32 warp tiles) ----------------
__global__ __launch_bounds__(THREADS, 1)
void gemm_kernel(const float* __restrict__ scale_ptr, float* __restrict__ out) {
    extern __shared__ __align__(16) char smem[];
    uint32_t sbase = smem_u32(smem);
    int tid = threadIdx.x;
    int wid = tid >> 5;

    int n0 = blockIdx.x * BN;
    int m0 = blockIdx.y * BM;

    // 16 warps laid out 4(M) x 4(N); warp tile 32x32 = 2x2 wmma tiles
    int wm = (wid >> 2) * 32;
    int wn = (wid & 3) * 32;

    auto load_stage = [&](int kc, int s) {
        uint32_t sA = sbase + s * STAGE_BYTES;
        uint32_t sB = sA + A_SM_BYTES;
        {   // A: 512 x 16B chunks, 1 per thread
            int row = tid >> 2, seg = tid & 3;
            cp_async16(sA + row * ASTRIDE + seg * 16,
                       &g_xh[(size_t)(m0 + row) * K_TOTAL + kc + seg * 8]);
        }
        {   // B: 512 x 16B chunks, 1 per thread
            int row = tid >> 2, seg = tid & 3;
            cp_async16(sB + row * ASTRIDE + seg * 16,
                       &g_b[(size_t)(n0 + row) * K_TOTAL + kc + seg * 8]);
        }
    };

    #pragma unroll
    for (int s = 0; s < STAGES - 1; s++) {
        load_stage(s * BK, s);
        asm volatile("cp.async.commit_group;" ::: "memory");
    }

    wmma::fragment<wmma::accumulator, 16, 16, 16, float> cf[2][2];
    #pragma unroll
    for (int mt = 0; mt < 2; mt++)
        #pragma unroll
        for (int nt = 0; nt < 2; nt++)
            wmma::fill_fragment(cf[mt][nt], 0.0f);

    for (int kc = 0; kc < NCHUNK; kc++) {
        asm volatile("cp.async.wait_group 2;" ::: "memory");
        __syncthreads();

        int pf = kc + STAGES - 1;
        if (pf < NCHUNK) load_stage(pf * BK, pf & (STAGES - 1));
        asm volatile("cp.async.commit_group;" ::: "memory");   // empty tail group keeps ids uniform

        int s = kc & (STAGES - 1);
        const char* stA = smem + s * STAGE_BYTES;
        const char* stB = stA + A_SM_BYTES;

        // load ALL fragments for both k16 steps first (regs allow it), then mma.
        // ptxas overlaps the later LDSMs with the earlier HMMAs.
        wmma::fragment<wmma::matrix_a, 16, 16, 16, __half, wmma::row_major> af[2][2];
        wmma::fragment<wmma::matrix_b, 16, 16, 16, __half, wmma::col_major> bf[2][2];
        #pragma unroll
        for (int ks = 0; ks < 2; ks++) {
            #pragma unroll
            for (int mt = 0; mt < 2; mt++)
                wmma::load_matrix_sync(af[ks][mt],
                    (const __half*)(stA + (wm + mt * 16) * ASTRIDE + ks * 32), 40);
        }
        #pragma unroll
        for (int nt = 0; nt < 2; nt++)
            wmma::load_matrix_sync(bf[0][nt],
                (const __half*)(stB + (wn + nt * 16) * ASTRIDE), 40);
        #pragma unroll
        for (int nt = 0; nt < 2; nt++)
            wmma::load_matrix_sync(bf[1][nt],
                (const __half*)(stB + (wn + nt * 16) * ASTRIDE + 32), 40);
        #pragma unroll
        for (int ks = 0; ks < 2; ks++)
            #pragma unroll
            for (int mt = 0; mt < 2; mt++)
                #pragma unroll
                for (int nt = 0; nt < 2; nt++)
                    wmma::mma_sync(cf[mt][nt], af[ks][mt], bf[ks][nt], cf[mt][nt]);
    }

    // ---- epilogue: scale in-fragment, store straight to gmem ----
    float sc = *scale_ptr;
    #pragma unroll
    for (int mt = 0; mt < 2; mt++) {
        #pragma unroll
        for (int nt = 0; nt < 2; nt++) {
            #pragma unroll
            for (int e = 0; e < cf[mt][nt].num_elements; e++)
                cf[mt][nt].x[e] *= sc;
            wmma::store_matrix_sync(
                out + (size_t)(m0 + wm + mt * 16) * N_TOTAL + (n0 + wn + nt * 16),
                cf[mt][nt], N_TOTAL, wmma::mem_row_major);
        }
    }
}

// ---------------- launch ----------------
extern "C" void kernel_launch(void* const* d_in, const int* in_sizes, int n_in,
                              void* d_out, int out_size) {
    // identify inputs by element count (robust to ordering)
    const float* x = nullptr;
    const void* kern = nullptr;
    const float* scale = nullptr;
    for (int i = 0; i < n_in; i++) {
        if (in_sizes[i] == M_TOTAL * K_TOTAL) x = (const float*)d_in[i];
        else if (in_sizes[i] == K_TOTAL * N_TOTAL) kern = (const void*)d_in[i];
        else if (in_sizes[i] == 1) scale = (const float*)d_in[i];
    }
    float* out = (float*)d_out;

    cudaFuncSetAttribute(gemm_kernel, cudaFuncAttributeMaxDynamicSharedMemorySize, SMEM_TOTAL);

    convert_x_kernel<<<(M_TOTAL * K_TOTAL) / (256 * 8), 256>>>(x);
    transpose_b_kernel<<<dim3(N_TOTAL / 32, K_TOTAL / 32), dim3(32, 8)>>>(kern);
    // grid.x = N tiles (adjacent CTAs share the A tile in L2), grid.y = M tiles
    gemm_kernel<<<dim3(N_TOTAL / BN, M_TOTAL / BM), THREADS, SMEM_TOTAL>>>(scale, out);
}

// round 7
// speedup vs baseline: 1.1363x; 1.1134x over previous
#include <cuda_runtime.h>
#include <cuda_fp16.h>
#include <cstdint>

// out[b,s,f] = scale * x[b,s,:] @ W, W = kernel ? +1 : -1
// GEMM: M=16384, K=1024, N=1024. Hand-rolled mma.sync m16n8k16 (validated in R2:
// produced identical output to wmma), fp32 accum.
// R7: R4's best config (256thr, 2 CTA/SM, 32x64 warp tile, 4 stages) + lean
// hand-rolled fragments so BOTH k16 steps' LDSMs issue before the mma bursts.

#define M_TOTAL 16384
#define N_TOTAL 1024
#define K_TOTAL 1024

#define BM 128
#define BN 128
#define BK 32
#define STAGES 4
#define NCHUNK (K_TOTAL / BK)      // 32
#define ASTRIDE 80                 // bytes per smem row: 64B data + 16B pad
#define A_SM_BYTES (BM * ASTRIDE)  // 10240
#define B_SM_BYTES (BN * ASTRIDE)  // 10240
#define STAGE_BYTES (A_SM_BYTES + B_SM_BYTES)   // 20480
#define SMEM_TOTAL (STAGES * STAGE_BYTES)       // 81920

__device__ __half g_xh[(size_t)M_TOTAL * K_TOTAL];   // 32 MB fp16 activations
__device__ __half g_b[(size_t)N_TOTAL * K_TOTAL];    // 2 MB, [n][k] = +/-1

// ---------------- helpers ----------------
__device__ __forceinline__ uint32_t smem_u32(const void* p) {
    uint32_t a;
    asm("{ .reg .u64 t; cvta.to.shared.u64 t, %1; cvt.u32.u64 %0, t; }" : "=r"(a) : "l"(p));
    return a;
}
__device__ __forceinline__ void cp_async16(uint32_t dst, const void* src) {
    asm volatile("cp.async.cg.shared.global [%0], [%1], 16;" :: "r"(dst), "l"(src) : "memory");
}
__device__ __forceinline__ void ldsm_x4(uint32_t& r0, uint32_t& r1, uint32_t& r2, uint32_t& r3,
                                        uint32_t addr) {
    asm volatile("ldmatrix.sync.aligned.m8n8.x4.shared.b16 {%0,%1,%2,%3}, [%4];"
                 : "=r"(r0), "=r"(r1), "=r"(r2), "=r"(r3) : "r"(addr));
}
__device__ __forceinline__ void mma16816(float* d, const uint32_t* a, const uint32_t* b) {
    asm volatile(
        "mma.sync.aligned.m16n8k16.row.col.f32.f16.f16.f32 "
        "{%0,%1,%2,%3}, {%4,%5,%6,%7}, {%8,%9}, {%0,%1,%2,%3};"
        : "+f"(d[0]), "+f"(d[1]), "+f"(d[2]), "+f"(d[3])
        : "r"(a[0]), "r"(a[1]), "r"(a[2]), "r"(a[3]), "r"(b[0]), "r"(b[1]));
}

// ---------------- prep kernels ----------------
__global__ void convert_x_kernel(const float* __restrict__ x) {
    size_t i = (size_t)blockIdx.x * blockDim.x + threadIdx.x;   // 8 floats per thread
    size_t base = i * 8;
    float4 a = *(const float4*)(x + base);
    float4 b = *(const float4*)(x + base + 4);
    __half2 h[4];
    h[0] = __floats2half2_rn(a.x, a.y);
    h[1] = __floats2half2_rn(a.z, a.w);
    h[2] = __floats2half2_rn(b.x, b.y);
    h[3] = __floats2half2_rn(b.z, b.w);
    *(uint4*)(&g_xh[base]) = *(uint4*)h;
}

// dtype-width detect (per block, redundant; L2-cached) + transpose to [n][k] +/-1
__global__ void transpose_b_kernel(const void* __restrict__ kern) {
    __shared__ unsigned char tile[32][33];
    __shared__ int notw, noth;
    int tx = threadIdx.x, ty = threadIdx.y;
    int t = ty * 32 + tx;
    if (t == 0) { notw = 0; noth = 0; }
    __syncthreads();
    const uint32_t* kw = (const uint32_t*)kern;
    for (int i = t; i < 1024; i += 256) {
        uint32_t w = kw[i];
        if (!(w == 0u || w == 1u || w == 0x3F800000u)) notw = 1;
        uint32_t h0 = w & 0xFFFFu, h1 = w >> 16;
        if (!((h0 == 0u || h0 == 1u || h0 == 0x3F80u || h0 == 0x3C00u) &&
              (h1 == 0u || h1 == 1u || h1 == 0x3F80u || h1 == 0x3C00u))) noth = 1;
    }
    __syncthreads();
    int width = (!notw) ? 4 : ((!noth) ? 2 : 1);

    int n0 = blockIdx.x * 32, k0 = blockIdx.y * 32;
    #pragma unroll
    for (int r = ty; r < 32; r += 8) {
        size_t idx = (size_t)(k0 + r) * N_TOTAL + n0 + tx;
        bool v = (width == 4) ? (((const uint32_t*)kern)[idx] != 0u)
               : (width == 2) ? (((const uint16_t*)kern)[idx] != 0u)
                              : (((const uint8_t*)kern)[idx] != 0u);
        tile[r][tx] = v ? 1 : 0;
    }
    __syncthreads();
    const __half pos = __float2half(1.0f), neg = __float2half(-1.0f);
    #pragma unroll
    for (int r = ty; r < 32; r += 8)
        g_b[(size_t)(n0 + r) * K_TOTAL + k0 + tx] = tile[tx][r] ? pos : neg;
}

// ---------------- GEMM (hand-rolled mma.sync multistage) ----------------
__global__ __launch_bounds__(256, 2)
void gemm_kernel(const float* __restrict__ scale_ptr, float* __restrict__ out) {
    extern __shared__ __align__(16) char smem[];
    uint32_t sbase = smem_u32(smem);
    int tid = threadIdx.x;
    int lane = tid & 31;
    int wid = tid >> 5;

    int n0 = blockIdx.x * BN;
    int m0 = blockIdx.y * BM;

    // warp tile: 32(M) x 64(N); warps laid out 4(M) x 2(N)
    int wm = (wid & 3) * 32;
    int wn = (wid >> 2) * 64;

    auto load_stage = [&](int kc, int s) {
        uint32_t sA = sbase + s * STAGE_BYTES;
        uint32_t sB = sA + A_SM_BYTES;
        #pragma unroll
        for (int i = 0; i < 2; i++) {           // A: 512 x 16B chunks / 256 threads
            int c = tid + i * 256;
            int row = c >> 2, seg = c & 3;
            cp_async16(sA + row * ASTRIDE + seg * 16,
                       &g_xh[(size_t)(m0 + row) * K_TOTAL + kc + seg * 8]);
        }
        #pragma unroll
        for (int i = 0; i < 2; i++) {           // B: 512 x 16B chunks
            int c = tid + i * 256;
            int row = c >> 2, seg = c & 3;
            cp_async16(sB + row * ASTRIDE + seg * 16,
                       &g_b[(size_t)(n0 + row) * K_TOTAL + kc + seg * 8]);
        }
    };

    #pragma unroll
    for (int s = 0; s < STAGES - 1; s++) {
        load_stage(s * BK, s);
        asm volatile("cp.async.commit_group;" ::: "memory");
    }

    float acc[2][8][4];
    #pragma unroll
    for (int mt = 0; mt < 2; mt++)
        #pragma unroll
        for (int nt = 0; nt < 8; nt++)
            #pragma unroll
            for (int j = 0; j < 4; j++) acc[mt][nt][j] = 0.0f;

    // ldmatrix lane-address components (constant per lane) — validated mapping (R2≡wmma)
    int r8 = lane & 7;
    int agrp_row = ((lane >> 3) & 1) * 8;
    int agrp_col = (lane >> 4) * 16;
    int bgrp = lane >> 3;
    int bgrp_row = (bgrp >> 1) * 8;
    int bgrp_col = (bgrp & 1) * 16;

    for (int kc = 0; kc < NCHUNK; kc++) {
        asm volatile("cp.async.wait_group 2;" ::: "memory");
        __syncthreads();

        int pf = kc + STAGES - 1;
        if (pf < NCHUNK) load_stage(pf * BK, pf & (STAGES - 1));
        asm volatile("cp.async.commit_group;" ::: "memory");   // empty tail group keeps ids uniform

        int s = kc & (STAGES - 1);
        uint32_t sA = sbase + s * STAGE_BYTES;
        uint32_t sB = sA + A_SM_BYTES;

        // ---- load ALL fragments for both k16 steps, then both mma bursts ----
        uint32_t a[2][2][4];   // [ks][mt][4]
        uint32_t b[2][8][2];   // [ks][nt][2]
        #pragma unroll
        for (int ks = 0; ks < 2; ks++) {
            #pragma unroll
            for (int mt = 0; mt < 2; mt++) {
                int row = wm + mt * 16 + agrp_row + r8;
                ldsm_x4(a[ks][mt][0], a[ks][mt][1], a[ks][mt][2], a[ks][mt][3],
                        sA + row * ASTRIDE + ks * 32 + agrp_col);
            }
            #pragma unroll
            for (int np = 0; np < 4; np++) {
                int n = wn + np * 16 + bgrp_row + r8;
                uint32_t r0, r1, r2, r3;
                ldsm_x4(r0, r1, r2, r3, sB + n * ASTRIDE + ks * 32 + bgrp_col);
                b[ks][2 * np][0] = r0;     b[ks][2 * np][1] = r1;
                b[ks][2 * np + 1][0] = r2; b[ks][2 * np + 1][1] = r3;
            }
        }
        #pragma unroll
        for (int ks = 0; ks < 2; ks++)
            #pragma unroll
            for (int mt = 0; mt < 2; mt++)
                #pragma unroll
                for (int nt = 0; nt < 8; nt++)
                    mma16816(acc[mt][nt], a[ks][mt], b[ks][nt]);
    }

    // ---- epilogue: scaled fp32 stores, one 32B sector per lane-quad ----
    float sc = *scale_ptr;
    int g = lane >> 2, t = lane & 3;
    #pragma unroll
    for (int mt = 0; mt < 2; mt++) {
        #pragma unroll
        for (int nt = 0; nt < 8; nt++) {
            int row = m0 + wm + mt * 16 + g;
            int col = n0 + wn + nt * 8 + 2 * t;
            float2 v0 = make_float2(acc[mt][nt][0] * sc, acc[mt][nt][1] * sc);
            float2 v1 = make_float2(acc[mt][nt][2] * sc, acc[mt][nt][3] * sc);
            *(float2*)(out + (size_t)row * N_TOTAL + col) = v0;
            *(float2*)(out + (size_t)(row + 8) * N_TOTAL + col) = v1;
        }
    }
}

// ---------------- launch ----------------
extern "C" void kernel_launch(void* const* d_in, const int* in_sizes, int n_in,
                              void* d_out, int out_size) {
    // identify inputs by element count (robust to ordering)
    const float* x = nullptr;
    const void* kern = nullptr;
    const float* scale = nullptr;
    for (int i = 0; i < n_in; i++) {
        if (in_sizes[i] == M_TOTAL * K_TOTAL) x = (const float*)d_in[i];
        else if (in_sizes[i] == K_TOTAL * N_TOTAL) kern = (const void*)d_in[i];
        else if (in_sizes[i] == 1) scale = (const float*)d_in[i];
    }
    float* out = (float*)d_out;

    cudaFuncSetAttribute(gemm_kernel, cudaFuncAttributeMaxDynamicSharedMemorySize, SMEM_TOTAL);

    convert_x_kernel<<<(M_TOTAL * K_TOTAL) / (256 * 8), 256>>>(x);
    transpose_b_kernel<<<dim3(N_TOTAL / 32, K_TOTAL / 32), dim3(32, 8)>>>(kern);
    // grid.x = N tiles (adjacent CTAs share the A tile in L2), grid.y = M tiles
    gemm_kernel<<<dim3(N_TOTAL / BN, M_TOTAL / BM), 256, SMEM_TOTAL>>>(scale, out);
}

// round 9
// speedup vs baseline: 1.3463x; 1.1848x over previous
#include <cuda_runtime.h>
#include <cuda_fp16.h>
#include <cstdint>

// out[b,s,f] = scale * x[b,s,:] @ W, W = kernel ? +1 : -1
// GEMM: M=16384, K=1024, N=1024. Hand-rolled mma.sync m16n8k16, fp32 accum.
// R9: R8's mbarrier-decoupled pipeline with the deadlock fixed:
// cp.async.mbarrier.arrive must be .noinc (plain form self-increments the
// expected count and the phase never flips -> R8 hang).

#define M_TOTAL 16384
#define N_TOTAL 1024
#define K_TOTAL 1024

#define BM 128
#define BN 128
#define BK 32
#define STAGES 4
#define NCHUNK (K_TOTAL / BK)      // 32
#define ASTRIDE 80                 // bytes per smem row: 64B data + 16B pad
#define A_SM_BYTES (BM * ASTRIDE)  // 10240
#define B_SM_BYTES (BN * ASTRIDE)  // 10240
#define STAGE_BYTES (A_SM_BYTES + B_SM_BYTES)   // 20480
#define SM_TILES 1024
#define SMEM_TOTAL (SM_TILES + STAGES * STAGE_BYTES)   // 82944

__device__ __half g_xh[(size_t)M_TOTAL * K_TOTAL];   // 32 MB fp16 activations
__device__ __half g_b[(size_t)N_TOTAL * K_TOTAL];    // 2 MB, [n][k] = +/-1

// ---------------- helpers ----------------
__device__ __forceinline__ uint32_t smem_u32(const void* p) {
    uint32_t a;
    asm("{ .reg .u64 t; cvta.to.shared.u64 t, %1; cvt.u32.u64 %0, t; }" : "=r"(a) : "l"(p));
    return a;
}
__device__ __forceinline__ void cp_async16(uint32_t dst, const void* src) {
    asm volatile("cp.async.cg.shared.global [%0], [%1], 16;" :: "r"(dst), "l"(src) : "memory");
}
__device__ __forceinline__ void ldsm_x4(uint32_t& r0, uint32_t& r1, uint32_t& r2, uint32_t& r3,
                                        uint32_t addr) {
    asm volatile("ldmatrix.sync.aligned.m8n8.x4.shared.b16 {%0,%1,%2,%3}, [%4];"
                 : "=r"(r0), "=r"(r1), "=r"(r2), "=r"(r3) : "r"(addr));
}
__device__ __forceinline__ void mma16816(float* d, const uint32_t* a, const uint32_t* b) {
    asm volatile(
        "mma.sync.aligned.m16n8k16.row.col.f32.f16.f16.f32 "
        "{%0,%1,%2,%3}, {%4,%5,%6,%7}, {%8,%9}, {%0,%1,%2,%3};"
        : "+f"(d[0]), "+f"(d[1]), "+f"(d[2]), "+f"(d[3])
        : "r"(a[0]), "r"(a[1]), "r"(a[2]), "r"(a[3]), "r"(b[0]), "r"(b[1]));
}
__device__ __forceinline__ void mbar_wait_parity(uint32_t mbar, uint32_t parity) {
    uint32_t done;
    asm volatile(
        "{ .reg .pred p; mbarrier.try_wait.parity.acquire.cta.shared::cta.b64 p, [%1], %2; selp.b32 %0, 1, 0, p; }"
        : "=r"(done) : "r"(mbar), "r"(parity) : "memory");
    if (!done) {
        asm volatile(
            "{ .reg .pred P1;\n"
            "WL_%=: mbarrier.try_wait.parity.acquire.cta.shared::cta.b64 P1, [%0], %1, 0x989680;\n"
            "@P1 bra.uni WD_%=;\n"
            "bra.uni WL_%=;\n"
            "WD_%=: }"
            :: "r"(mbar), "r"(parity) : "memory");
    }
}

// ---------------- prep kernels ----------------
__global__ void convert_x_kernel(const float* __restrict__ x) {
    size_t i = (size_t)blockIdx.x * blockDim.x + threadIdx.x;   // 8 floats per thread
    size_t base = i * 8;
    float4 a = *(const float4*)(x + base);
    float4 b = *(const float4*)(x + base + 4);
    __half2 h[4];
    h[0] = __floats2half2_rn(a.x, a.y);
    h[1] = __floats2half2_rn(a.z, a.w);
    h[2] = __floats2half2_rn(b.x, b.y);
    h[3] = __floats2half2_rn(b.z, b.w);
    *(uint4*)(&g_xh[base]) = *(uint4*)h;
}

// dtype-width detect (per block, redundant; L2-cached) + transpose to [n][k] +/-1
__global__ void transpose_b_kernel(const void* __restrict__ kern) {
    __shared__ unsigned char tile[32][33];
    __shared__ int notw, noth;
    int tx = threadIdx.x, ty = threadIdx.y;
    int t = ty * 32 + tx;
    if (t == 0) { notw = 0; noth = 0; }
    __syncthreads();
    const uint32_t* kw = (const uint32_t*)kern;
    for (int i = t; i < 1024; i += 256) {
        uint32_t w = kw[i];
        if (!(w == 0u || w == 1u || w == 0x3F800000u)) notw = 1;
        uint32_t h0 = w & 0xFFFFu, h1 = w >> 16;
        if (!((h0 == 0u || h0 == 1u || h0 == 0x3F80u || h0 == 0x3C00u) &&
              (h1 == 0u || h1 == 1u || h1 == 0x3F80u || h1 == 0x3C00u))) noth = 1;
    }
    __syncthreads();
    int width = (!notw) ? 4 : ((!noth) ? 2 : 1);

    int n0 = blockIdx.x * 32, k0 = blockIdx.y * 32;
    #pragma unroll
    for (int r = ty; r < 32; r += 8) {
        size_t idx = (size_t)(k0 + r) * N_TOTAL + n0 + tx;
        bool v = (width == 4) ? (((const uint32_t*)kern)[idx] != 0u)
               : (width == 2) ? (((const uint16_t*)kern)[idx] != 0u)
                              : (((const uint8_t*)kern)[idx] != 0u);
        tile[r][tx] = v ? 1 : 0;
    }
    __syncthreads();
    const __half pos = __float2half(1.0f), neg = __float2half(-1.0f);
    #pragma unroll
    for (int r = ty; r < 32; r += 8)
        g_b[(size_t)(n0 + r) * K_TOTAL + k0 + tx] = tile[tx][r] ? pos : neg;
}

// ---------------- GEMM (mma.sync, mbarrier-decoupled multistage) ----------------
__global__ __launch_bounds__(256, 2)
void gemm_kernel(const float* __restrict__ scale_ptr, float* __restrict__ out) {
    extern __shared__ __align__(16) char smem[];
    uint32_t sbase = smem_u32(smem);
    int tid = threadIdx.x;
    int lane = tid & 31;
    int wid = tid >> 5;

    int n0 = blockIdx.x * BN;
    int m0 = blockIdx.y * BM;

    // warp tile: 32(M) x 64(N); warps laid out 4(M) x 2(N)
    int wm = (wid & 3) * 32;
    int wn = (wid >> 2) * 64;

    // mbarriers: full[s] at sbase + s*8, empty[s] at sbase + 32 + s*8
    if (tid == 0) {
        #pragma unroll
        for (int s = 0; s < STAGES; s++) {
            asm volatile("mbarrier.init.shared.b64 [%0], %1;" :: "r"(sbase + s * 8), "r"(256) : "memory");
            asm volatile("mbarrier.init.shared.b64 [%0], %1;" :: "r"(sbase + 32 + s * 8), "r"(256) : "memory");
        }
    }
    __syncthreads();

    auto load_stage = [&](int kc, int s) {
        uint32_t sA = sbase + SM_TILES + s * STAGE_BYTES;
        uint32_t sB = sA + A_SM_BYTES;
        #pragma unroll
        for (int i = 0; i < 2; i++) {           // A: 512 x 16B chunks / 256 threads
            int c = tid + i * 256;
            int row = c >> 2, seg = c & 3;
            cp_async16(sA + row * ASTRIDE + seg * 16,
                       &g_xh[(size_t)(m0 + row) * K_TOTAL + kc + seg * 8]);
        }
        #pragma unroll
        for (int i = 0; i < 2; i++) {           // B: 512 x 16B chunks
            int c = tid + i * 256;
            int row = c >> 2, seg = c & 3;
            cp_async16(sB + row * ASTRIDE + seg * 16,
                       &g_b[(size_t)(n0 + row) * K_TOTAL + kc + seg * 8]);
        }
        // .noinc: this thread's single expected arrival fires when its
        // cp.asyncs above complete (plain form would self-increment -> hang)
        asm volatile("cp.async.mbarrier.arrive.noinc.shared::cta.b64 [%0];"
                     :: "r"(sbase + s * 8) : "memory");
    };

    // prologue: fill stages 0..2
    #pragma unroll
    for (int s = 0; s < STAGES - 1; s++)
        load_stage(s * BK, s);

    float acc[2][8][4];
    #pragma unroll
    for (int mt = 0; mt < 2; mt++)
        #pragma unroll
        for (int nt = 0; nt < 8; nt++)
            #pragma unroll
            for (int j = 0; j < 4; j++) acc[mt][nt][j] = 0.0f;

    // ldmatrix lane-address components (validated mapping, R2 == wmma)
    int r8 = lane & 7;
    int agrp_row = ((lane >> 3) & 1) * 8;
    int agrp_col = (lane >> 4) * 16;
    int bgrp = lane >> 3;
    int bgrp_row = (bgrp >> 1) * 8;
    int bgrp_col = (bgrp & 1) * 16;

    for (int kc = 0; kc < NCHUNK; kc++) {
        // -------- producer: fill stage for chunk kc+3 --------
        int pf = kc + STAGES - 1;
        if (pf < NCHUNK) {
            int ps = pf & (STAGES - 1);
            int rp = pf >> 2;                       // round of pf
            if (rp >= 1)                            // stage previously used: wait readers
                mbar_wait_parity(sbase + 32 + ps * 8, (rp - 1) & 1);
            load_stage(pf * BK, ps);
        }

        // -------- consumer: chunk kc --------
        int s = kc & (STAGES - 1);
        int r = kc >> 2;
        mbar_wait_parity(sbase + s * 8, r & 1);     // wait stage full

        uint32_t sA = sbase + SM_TILES + s * STAGE_BYTES;
        uint32_t sB = sA + A_SM_BYTES;

        #pragma unroll
        for (int ks = 0; ks < 2; ks++) {
            uint32_t b[8][2];
            #pragma unroll
            for (int np = 0; np < 4; np++) {
                int n = wn + np * 16 + bgrp_row + r8;
                uint32_t r0, r1, r2, r3;
                ldsm_x4(r0, r1, r2, r3, sB + n * ASTRIDE + ks * 32 + bgrp_col);
                b[2 * np][0] = r0;     b[2 * np][1] = r1;
                b[2 * np + 1][0] = r2; b[2 * np + 1][1] = r3;
            }
            #pragma unroll
            for (int mt = 0; mt < 2; mt++) {
                int row = wm + mt * 16 + agrp_row + r8;
                uint32_t a[4];
                ldsm_x4(a[0], a[1], a[2], a[3], sA + row * ASTRIDE + ks * 32 + agrp_col);
                #pragma unroll
                for (int nt = 0; nt < 8; nt++)
                    mma16816(acc[mt][nt], a, b[nt]);
            }
        }
        // reads of stage s done (ldmatrix.sync is synchronous): release it
        asm volatile("mbarrier.arrive.shared.b64 _, [%0];" :: "r"(sbase + 32 + s * 8) : "memory");
    }

    // ---- epilogue: scaled fp32 stores, one 32B sector per lane-quad ----
    float sc = *scale_ptr;
    int g = lane >> 2, t = lane & 3;
    #pragma unroll
    for (int mt = 0; mt < 2; mt++) {
        #pragma unroll
        for (int nt = 0; nt < 8; nt++) {
            int row = m0 + wm + mt * 16 + g;
            int col = n0 + wn + nt * 8 + 2 * t;
            float2 v0 = make_float2(acc[mt][nt][0] * sc, acc[mt][nt][1] * sc);
            float2 v1 = make_float2(acc[mt][nt][2] * sc, acc[mt][nt][3] * sc);
            *(float2*)(out + (size_t)row * N_TOTAL + col) = v0;
            *(float2*)(out + (size_t)(row + 8) * N_TOTAL + col) = v1;
        }
    }
}

// ---------------- launch ----------------
extern "C" void kernel_launch(void* const* d_in, const int* in_sizes, int n_in,
                              void* d_out, int out_size) {
    // identify inputs by element count (robust to ordering)
    const float* x = nullptr;
    const void* kern = nullptr;
    const float* scale = nullptr;
    for (int i = 0; i < n_in; i++) {
        if (in_sizes[i] == M_TOTAL * K_TOTAL) x = (const float*)d_in[i];
        else if (in_sizes[i] == K_TOTAL * N_TOTAL) kern = (const void*)d_in[i];
        else if (in_sizes[i] == 1) scale = (const float*)d_in[i];
    }
    float* out = (float*)d_out;

    cudaFuncSetAttribute(gemm_kernel, cudaFuncAttributeMaxDynamicSharedMemorySize, SMEM_TOTAL);

    convert_x_kernel<<<(M_TOTAL * K_TOTAL) / (256 * 8), 256>>>(x);
    transpose_b_kernel<<<dim3(N_TOTAL / 32, K_TOTAL / 32), dim3(32, 8)>>>(kern);
    // grid.x = N tiles (adjacent CTAs share the A tile in L2), grid.y = M tiles
    gemm_kernel<<<dim3(N_TOTAL / BN, M_TOTAL / BM), 256, SMEM_TOTAL>>>(scale, out);
}

// round 10
// speedup vs baseline: 1.3965x; 1.0373x over previous
#include <cuda_runtime.h>
#include <cuda_fp16.h>
#include <cstdint>

// out[b,s,f] = scale * x[b,s,:] @ W, W = kernel ? +1 : -1
// GEMM: M=16384, K=1024, N=1024. mma.sync m16n8k16, fp32 accum.
// R10: B stored as 1 byte/value (fp16 high byte 0x3C/0xBC) in mma-fragment
// order; expanded in-register via PRMT. Halves the binding smem traffic.

#define M_TOTAL 16384
#define N_TOTAL 1024
#define K_TOTAL 1024

#define BM 128
#define BN 128
#define BK 32
#define STAGES 4
#define NCHUNK (K_TOTAL / BK)      // 32
#define ASTRIDE 80                 // A smem row: 64B data + 16B pad
#define A_SM_BYTES (BM * ASTRIDE)  // 10240
#define B_SM_BYTES 4096            // 2 nb-blocks x 2048B fragment-ordered bytes
#define STAGE_BYTES (A_SM_BYTES + B_SM_BYTES)   // 14336
#define SM_TILES 1024
#define SMEM_TOTAL (SM_TILES + STAGES * STAGE_BYTES)   // 58368

__device__ __half g_xh[(size_t)M_TOTAL * K_TOTAL];        // 32 MB fp16 activations
__device__ unsigned char g_b8[(size_t)N_TOTAL * K_TOTAL]; // 1 MB fragment-ordered B bytes

// ---------------- helpers ----------------
__device__ __forceinline__ uint32_t smem_u32(const void* p) {
    uint32_t a;
    asm("{ .reg .u64 t; cvta.to.shared.u64 t, %1; cvt.u32.u64 %0, t; }" : "=r"(a) : "l"(p));
    return a;
}
__device__ __forceinline__ void cp_async16(uint32_t dst, const void* src) {
    asm volatile("cp.async.cg.shared.global [%0], [%1], 16;" :: "r"(dst), "l"(src) : "memory");
}
__device__ __forceinline__ void ldsm_x4(uint32_t& r0, uint32_t& r1, uint32_t& r2, uint32_t& r3,
                                        uint32_t addr) {
    asm volatile("ldmatrix.sync.aligned.m8n8.x4.shared.b16 {%0,%1,%2,%3}, [%4];"
                 : "=r"(r0), "=r"(r1), "=r"(r2), "=r"(r3) : "r"(addr));
}
__device__ __forceinline__ void lds128(uint32_t& r0, uint32_t& r1, uint32_t& r2, uint32_t& r3,
                                       uint32_t addr) {
    asm volatile("ld.shared.v4.u32 {%0,%1,%2,%3}, [%4];"
                 : "=r"(r0), "=r"(r1), "=r"(r2), "=r"(r3) : "r"(addr));
}
__device__ __forceinline__ uint32_t prmt(uint32_t a, uint32_t sel) {
    uint32_t d;
    asm("prmt.b32 %0, %1, %2, %3;" : "=r"(d) : "r"(a), "r"(0u), "r"(sel));
    return d;
}
__device__ __forceinline__ void mma16816(float* d, const uint32_t* a, const uint32_t* b) {
    asm volatile(
        "mma.sync.aligned.m16n8k16.row.col.f32.f16.f16.f32 "
        "{%0,%1,%2,%3}, {%4,%5,%6,%7}, {%8,%9}, {%0,%1,%2,%3};"
        : "+f"(d[0]), "+f"(d[1]), "+f"(d[2]), "+f"(d[3])
        : "r"(a[0]), "r"(a[1]), "r"(a[2]), "r"(a[3]), "r"(b[0]), "r"(b[1]));
}
__device__ __forceinline__ void mbar_wait_parity(uint32_t mbar, uint32_t parity) {
    uint32_t done;
    asm volatile(
        "{ .reg .pred p; mbarrier.try_wait.parity.acquire.cta.shared::cta.b64 p, [%1], %2; selp.b32 %0, 1, 0, p; }"
        : "=r"(done) : "r"(mbar), "r"(parity) : "memory");
    if (!done) {
        asm volatile(
            "{ .reg .pred P1;\n"
            "WL_%=: mbarrier.try_wait.parity.acquire.cta.shared::cta.b64 P1, [%0], %1, 0x989680;\n"
            "@P1 bra.uni WD_%=;\n"
            "bra.uni WL_%=;\n"
            "WD_%=: }"
            :: "r"(mbar), "r"(parity) : "memory");
    }
}

// ---------------- prep kernels ----------------
__global__ void convert_x_kernel(const float* __restrict__ x) {
    size_t i = (size_t)blockIdx.x * blockDim.x + threadIdx.x;   // 8 floats per thread
    size_t base = i * 8;
    float4 a = *(const float4*)(x + base);
    float4 b = *(const float4*)(x + base + 4);
    __half2 h[4];
    h[0] = __floats2half2_rn(a.x, a.y);
    h[1] = __floats2half2_rn(a.z, a.w);
    h[2] = __floats2half2_rn(b.x, b.y);
    h[3] = __floats2half2_rn(b.z, b.w);
    *(uint4*)(&g_xh[base]) = *(uint4*)h;
}

// Pack B into mma-fragment byte order (+ dtype-width detect per block).
// Byte address = ((kc*16 + nb)*2 + ks)*1024 + q*512 + lane*16 + (nt'*4 + reg*2 + e)
//   where nt = q*4 + nt', n = nb*64 + nt*8 + lane/4,
//         k = kc*32 + ks*16 + reg*8 + 2*(lane&3) + e.
__global__ void pack_b_kernel(const void* __restrict__ kern) {
    __shared__ int notw, noth;
    int t = threadIdx.x;
    if (t == 0) { notw = 0; noth = 0; }
    __syncthreads();
    const uint32_t* kw = (const uint32_t*)kern;
    for (int i = t; i < 1024; i += 256) {
        uint32_t w = kw[i];
        if (!(w == 0u || w == 1u || w == 0x3F800000u)) notw = 1;
        uint32_t h0 = w & 0xFFFFu, h1 = w >> 16;
        if (!((h0 == 0u || h0 == 1u || h0 == 0x3F80u || h0 == 0x3C00u) &&
              (h1 == 0u || h1 == 1u || h1 == 0x3F80u || h1 == 0x3C00u))) noth = 1;
    }
    __syncthreads();
    int width = (!notw) ? 4 : ((!noth) ? 2 : 1);

    int gid = blockIdx.x * 256 + t;        // 65536 groups x 16 bytes
    int lane = gid & 31;
    int q = (gid >> 5) & 1;
    int ks = (gid >> 6) & 1;
    int blk = gid >> 7;                    // kc*16 + nb
    int kc = blk >> 4;
    int nb = blk & 15;

    unsigned char bytes[16];
    #pragma unroll
    for (int j = 0; j < 16; j++) {
        int nt = q * 4 + (j >> 2);
        int reg = (j >> 1) & 1;
        int e = j & 1;
        int n = nb * 64 + nt * 8 + (lane >> 2);
        int k = kc * 32 + ks * 16 + reg * 8 + 2 * (lane & 3) + e;
        size_t idx = (size_t)k * N_TOTAL + n;
        bool v = (width == 4) ? (((const uint32_t*)kern)[idx] != 0u)
               : (width == 2) ? (((const uint16_t*)kern)[idx] != 0u)
                              : (((const uint8_t*)kern)[idx] != 0u);
        bytes[j] = v ? 0x3C : 0xBC;        // fp16 high byte of +1 / -1
    }
    *(uint4*)&g_b8[(size_t)gid * 16] = *(uint4*)bytes;
}

// ---------------- GEMM (mma.sync, mbarrier-decoupled, byte-B) ----------------
__global__ __launch_bounds__(256, 2)
void gemm_kernel(const float* __restrict__ scale_ptr, float* __restrict__ out) {
    extern __shared__ __align__(16) char smem[];
    uint32_t sbase = smem_u32(smem);
    int tid = threadIdx.x;
    int lane = tid & 31;
    int wid = tid >> 5;

    int n0 = blockIdx.x * BN;
    int m0 = blockIdx.y * BM;
    int nb0 = n0 >> 6;                     // first 64-wide n-block of this CTA

    // warp tile: 32(M) x 64(N); warps laid out 4(M) x 2(N)
    int wm = (wid & 3) * 32;
    int wn = (wid >> 2) * 64;
    int nbl = wn >> 6;                     // 0 or 1: local n-block

    // mbarriers: full[s] at sbase + s*8, empty[s] at sbase + 32 + s*8
    if (tid == 0) {
        #pragma unroll
        for (int s = 0; s < STAGES; s++) {
            asm volatile("mbarrier.init.shared.b64 [%0], %1;" :: "r"(sbase + s * 8), "r"(256) : "memory");
            asm volatile("mbarrier.init.shared.b64 [%0], %1;" :: "r"(sbase + 32 + s * 8), "r"(256) : "memory");
        }
    }
    __syncthreads();

    auto load_stage = [&](int kc, int s) {
        uint32_t sA = sbase + SM_TILES + s * STAGE_BYTES;
        uint32_t sB = sA + A_SM_BYTES;
        #pragma unroll
        for (int i = 0; i < 2; i++) {           // A: 512 x 16B chunks / 256 threads
            int c = tid + i * 256;
            int row = c >> 2, seg = c & 3;
            cp_async16(sA + row * ASTRIDE + seg * 16,
                       &g_xh[(size_t)(m0 + row) * K_TOTAL + kc * BK + seg * 8]);
        }
        {   // B: 256 x 16B fragment-ordered byte chunks, 1 per thread
            int nbl_t = tid >> 7;               // 0 or 1
            int off = (tid & 127) * 16;
            cp_async16(sB + nbl_t * 2048 + off,
                       &g_b8[((size_t)(kc * 16 + nb0 + nbl_t)) * 2048 + off]);
        }
        // .noinc: one expected arrival per thread when its cp.asyncs complete
        asm volatile("cp.async.mbarrier.arrive.noinc.shared::cta.b64 [%0];"
                     :: "r"(sbase + s * 8) : "memory");
    };

    // prologue: fill stages 0..2
    #pragma unroll
    for (int s = 0; s < STAGES - 1; s++)
        load_stage(s, s);

    float acc[2][8][4];
    #pragma unroll
    for (int mt = 0; mt < 2; mt++)
        #pragma unroll
        for (int nt = 0; nt < 8; nt++)
            #pragma unroll
            for (int j = 0; j < 4; j++) acc[mt][nt][j] = 0.0f;

    // A ldmatrix lane-address components (validated mapping)
    int r8 = lane & 7;
    int agrp_row = ((lane >> 3) & 1) * 8;
    int agrp_col = (lane >> 4) * 16;

    for (int kc = 0; kc < NCHUNK; kc++) {
        // -------- producer: fill stage for chunk kc+3 --------
        int pf = kc + STAGES - 1;
        if (pf < NCHUNK) {
            int ps = pf & (STAGES - 1);
            int rp = pf >> 2;
            if (rp >= 1)
                mbar_wait_parity(sbase + 32 + ps * 8, (rp - 1) & 1);
            load_stage(pf, ps);
        }

        // -------- consumer: chunk kc --------
        int s = kc & (STAGES - 1);
        int r = kc >> 2;
        mbar_wait_parity(sbase + s * 8, r & 1);

        uint32_t sA = sbase + SM_TILES + s * STAGE_BYTES;
        uint32_t sB = sA + A_SM_BYTES;

        #pragma unroll
        for (int ks = 0; ks < 2; ks++) {
            // B: 2 x LDS.128 -> 8 words; word nt -> 2 half2 regs via PRMT
            uint32_t bw[8];
            uint32_t baddr = sB + nbl * 2048 + ks * 1024 + lane * 16;
            lds128(bw[0], bw[1], bw[2], bw[3], baddr);
            lds128(bw[4], bw[5], bw[6], bw[7], baddr + 512);
            uint32_t b[8][2];
            #pragma unroll
            for (int nt = 0; nt < 8; nt++) {
                b[nt][0] = prmt(bw[nt], 0x1404u);   // [00,H(e0),00,H(e1)]
                b[nt][1] = prmt(bw[nt], 0x3424u);
            }
            #pragma unroll
            for (int mt = 0; mt < 2; mt++) {
                int row = wm + mt * 16 + agrp_row + r8;
                uint32_t a[4];
                ldsm_x4(a[0], a[1], a[2], a[3], sA + row * ASTRIDE + ks * 32 + agrp_col);
                #pragma unroll
                for (int nt = 0; nt < 8; nt++)
                    mma16816(acc[mt][nt], a, b[nt]);
            }
        }
        // reads of stage s done: release it
        asm volatile("mbarrier.arrive.shared.b64 _, [%0];" :: "r"(sbase + 32 + s * 8) : "memory");
    }

    // ---- epilogue: scaled fp32 stores, one 32B sector per lane-quad ----
    float sc = *scale_ptr;
    int g = lane >> 2, t = lane & 3;
    #pragma unroll
    for (int mt = 0; mt < 2; mt++) {
        #pragma unroll
        for (int nt = 0; nt < 8; nt++) {
            int row = m0 + wm + mt * 16 + g;
            int col = n0 + wn + nt * 8 + 2 * t;
            float2 v0 = make_float2(acc[mt][nt][0] * sc, acc[mt][nt][1] * sc);
            float2 v1 = make_float2(acc[mt][nt][2] * sc, acc[mt][nt][3] * sc);
            *(float2*)(out + (size_t)row * N_TOTAL + col) = v0;
            *(float2*)(out + (size_t)(row + 8) * N_TOTAL + col) = v1;
        }
    }
}

// ---------------- launch ----------------
extern "C" void kernel_launch(void* const* d_in, const int* in_sizes, int n_in,
                              void* d_out, int out_size) {
    // identify inputs by element count (robust to ordering)
    const float* x = nullptr;
    const void* kern = nullptr;
    const float* scale = nullptr;
    for (int i = 0; i < n_in; i++) {
        if (in_sizes[i] == M_TOTAL * K_TOTAL) x = (const float*)d_in[i];
        else if (in_sizes[i] == K_TOTAL * N_TOTAL) kern = (const void*)d_in[i];
        else if (in_sizes[i] == 1) scale = (const float*)d_in[i];
    }
    float* out = (float*)d_out;

    cudaFuncSetAttribute(gemm_kernel, cudaFuncAttributeMaxDynamicSharedMemorySize, SMEM_TOTAL);

    convert_x_kernel<<<(M_TOTAL * K_TOTAL) / (256 * 8), 256>>>(x);
    pack_b_kernel<<<256, 256>>>(kern);
    // grid.x = N tiles (adjacent CTAs share the A tile in L2), grid.y = M tiles
    gemm_kernel<<<dim3(N_TOTAL / BN, M_TOTAL / BM), 256, SMEM_TOTAL>>>(scale, out);
}

// round 12
// speedup vs baseline: 1.5013x; 1.0751x over previous
#include <cuda_runtime.h>
#include <cuda_fp16.h>
#include <cstdint>

// out[b,s,f] = scale * x[b,s,:] @ W, W = kernel ? +1 : -1
// GEMM: M=16384, K=1024, N=1024. mma.sync m16n8k16, fp32 accum.
// R12: R11 (merged prep + 6 stages) with the producer parity bug fixed:
// p_ephase starts at 1 so the first wrap yields parity 0 for the first
// reuse cycle (R11 waited parity 1 against a phase-0 release -> hang).

#define M_TOTAL 16384
#define N_TOTAL 1024
#define K_TOTAL 1024

#define BM 128
#define BN 128
#define BK 32
#define STAGES 6
#define NCHUNK (K_TOTAL / BK)      // 32
#define ASTRIDE 80                 // A smem row: 64B data + 16B pad
#define A_SM_BYTES (BM * ASTRIDE)  // 10240
#define B_SM_BYTES 4096            // 2 nb-blocks x 2048B fragment-ordered bytes
#define STAGE_BYTES (A_SM_BYTES + B_SM_BYTES)   // 14336
#define SM_TILES 1024
#define SMEM_TOTAL (SM_TILES + STAGES * STAGE_BYTES)   // 87040

__device__ __half g_xh[(size_t)M_TOTAL * K_TOTAL];        // 32 MB fp16 activations
__device__ unsigned char g_b8[(size_t)N_TOTAL * K_TOTAL]; // 1 MB fragment-ordered B bytes

// ---------------- helpers ----------------
__device__ __forceinline__ uint32_t smem_u32(const void* p) {
    uint32_t a;
    asm("{ .reg .u64 t; cvta.to.shared.u64 t, %1; cvt.u32.u64 %0, t; }" : "=r"(a) : "l"(p));
    return a;
}
__device__ __forceinline__ void cp_async16(uint32_t dst, const void* src) {
    asm volatile("cp.async.cg.shared.global [%0], [%1], 16;" :: "r"(dst), "l"(src) : "memory");
}
__device__ __forceinline__ void ldsm_x4(uint32_t& r0, uint32_t& r1, uint32_t& r2, uint32_t& r3,
                                        uint32_t addr) {
    asm volatile("ldmatrix.sync.aligned.m8n8.x4.shared.b16 {%0,%1,%2,%3}, [%4];"
                 : "=r"(r0), "=r"(r1), "=r"(r2), "=r"(r3) : "r"(addr));
}
__device__ __forceinline__ void lds128(uint32_t& r0, uint32_t& r1, uint32_t& r2, uint32_t& r3,
                                       uint32_t addr) {
    asm volatile("ld.shared.v4.u32 {%0,%1,%2,%3}, [%4];"
                 : "=r"(r0), "=r"(r1), "=r"(r2), "=r"(r3) : "r"(addr));
}
__device__ __forceinline__ uint32_t prmt(uint32_t a, uint32_t sel) {
    uint32_t d;
    asm("prmt.b32 %0, %1, %2, %3;" : "=r"(d) : "r"(a), "r"(0u), "r"(sel));
    return d;
}
__device__ __forceinline__ void mma16816(float* d, const uint32_t* a, const uint32_t* b) {
    asm volatile(
        "mma.sync.aligned.m16n8k16.row.col.f32.f16.f16.f32 "
        "{%0,%1,%2,%3}, {%4,%5,%6,%7}, {%8,%9}, {%0,%1,%2,%3};"
        : "+f"(d[0]), "+f"(d[1]), "+f"(d[2]), "+f"(d[3])
        : "r"(a[0]), "r"(a[1]), "r"(a[2]), "r"(a[3]), "r"(b[0]), "r"(b[1]));
}
__device__ __forceinline__ void mbar_wait_parity(uint32_t mbar, uint32_t parity) {
    uint32_t done;
    asm volatile(
        "{ .reg .pred p; mbarrier.try_wait.parity.acquire.cta.shared::cta.b64 p, [%1], %2; selp.b32 %0, 1, 0, p; }"
        : "=r"(done) : "r"(mbar), "r"(parity) : "memory");
    if (!done) {
        asm volatile(
            "{ .reg .pred P1;\n"
            "WL_%=: mbarrier.try_wait.parity.acquire.cta.shared::cta.b64 P1, [%0], %1, 0x989680;\n"
            "@P1 bra.uni WD_%=;\n"
            "bra.uni WL_%=;\n"
            "WD_%=: }"
            :: "r"(mbar), "r"(parity) : "memory");
    }
}

// ---------------- merged prep kernel ----------------
// blocks [0,256): pack B bytes (fragment order, dtype auto-detect).
// blocks [256, 256+8192): fp32 -> fp16 convert of x.
__global__ void prep_kernel(const float* __restrict__ x, const void* __restrict__ kern) {
    if (blockIdx.x >= 256) {
        // ---- convert x ----
        size_t i = (size_t)(blockIdx.x - 256) * blockDim.x + threadIdx.x;  // 8 floats per thread
        size_t base = i * 8;
        float4 a = *(const float4*)(x + base);
        float4 b = *(const float4*)(x + base + 4);
        __half2 h[4];
        h[0] = __floats2half2_rn(a.x, a.y);
        h[1] = __floats2half2_rn(a.z, a.w);
        h[2] = __floats2half2_rn(b.x, b.y);
        h[3] = __floats2half2_rn(b.z, b.w);
        *(uint4*)(&g_xh[base]) = *(uint4*)h;
        return;
    }

    // ---- pack B (with per-block dtype-width detection; L2-cached scan) ----
    __shared__ int notw, noth;
    int t = threadIdx.x;
    if (t == 0) { notw = 0; noth = 0; }
    __syncthreads();
    const uint32_t* kw = (const uint32_t*)kern;
    for (int i = t; i < 1024; i += 256) {
        uint32_t w = kw[i];
        if (!(w == 0u || w == 1u || w == 0x3F800000u)) notw = 1;
        uint32_t h0 = w & 0xFFFFu, h1 = w >> 16;
        if (!((h0 == 0u || h0 == 1u || h0 == 0x3F80u || h0 == 0x3C00u) &&
              (h1 == 0u || h1 == 1u || h1 == 0x3F80u || h1 == 0x3C00u))) noth = 1;
    }
    __syncthreads();
    int width = (!notw) ? 4 : ((!noth) ? 2 : 1);

    int gid = blockIdx.x * 256 + t;        // 65536 groups x 16 bytes
    int lane = gid & 31;
    int q = (gid >> 5) & 1;
    int ks = (gid >> 6) & 1;
    int blk = gid >> 7;                    // kc*16 + nb
    int kc = blk >> 4;
    int nb = blk & 15;

    unsigned char bytes[16];
    #pragma unroll
    for (int j = 0; j < 16; j++) {
        int nt = q * 4 + (j >> 2);
        int reg = (j >> 1) & 1;
        int e = j & 1;
        int n = nb * 64 + nt * 8 + (lane >> 2);
        int k = kc * 32 + ks * 16 + reg * 8 + 2 * (lane & 3) + e;
        size_t idx = (size_t)k * N_TOTAL + n;
        bool v = (width == 4) ? (((const uint32_t*)kern)[idx] != 0u)
               : (width == 2) ? (((const uint16_t*)kern)[idx] != 0u)
                              : (((const uint8_t*)kern)[idx] != 0u);
        bytes[j] = v ? 0x3C : 0xBC;        // fp16 high byte of +1 / -1
    }
    *(uint4*)&g_b8[(size_t)gid * 16] = *(uint4*)bytes;
}

// ---------------- GEMM (mma.sync, mbarrier-decoupled, byte-B, 6 stages) ----------------
__global__ __launch_bounds__(256, 2)
void gemm_kernel(const float* __restrict__ scale_ptr, float* __restrict__ out) {
    extern __shared__ __align__(16) char smem[];
    uint32_t sbase = smem_u32(smem);
    int tid = threadIdx.x;
    int lane = tid & 31;
    int wid = tid >> 5;

    int n0 = blockIdx.x * BN;
    int m0 = blockIdx.y * BM;
    int nb0 = n0 >> 6;                     // first 64-wide n-block of this CTA

    // warp tile: 32(M) x 64(N); warps laid out 4(M) x 2(N)
    int wm = (wid & 3) * 32;
    int wn = (wid >> 2) * 64;
    int nbl = wn >> 6;                     // 0 or 1: local n-block

    // mbarriers: full[s] at sbase + s*8 (s<6), empty[s] at sbase + 64 + s*8
    if (tid == 0) {
        #pragma unroll
        for (int s = 0; s < STAGES; s++) {
            asm volatile("mbarrier.init.shared.b64 [%0], %1;" :: "r"(sbase + s * 8), "r"(256) : "memory");
            asm volatile("mbarrier.init.shared.b64 [%0], %1;" :: "r"(sbase + 64 + s * 8), "r"(256) : "memory");
        }
    }
    __syncthreads();

    auto load_stage = [&](int kc, int s) {
        uint32_t sA = sbase + SM_TILES + s * STAGE_BYTES;
        uint32_t sB = sA + A_SM_BYTES;
        #pragma unroll
        for (int i = 0; i < 2; i++) {           // A: 512 x 16B chunks / 256 threads
            int c = tid + i * 256;
            int row = c >> 2, seg = c & 3;
            cp_async16(sA + row * ASTRIDE + seg * 16,
                       &g_xh[(size_t)(m0 + row) * K_TOTAL + kc * BK + seg * 8]);
        }
        {   // B: 256 x 16B fragment-ordered byte chunks, 1 per thread
            int nbl_t = tid >> 7;               // 0 or 1
            int off = (tid & 127) * 16;
            cp_async16(sB + nbl_t * 2048 + off,
                       &g_b8[((size_t)(kc * 16 + nb0 + nbl_t)) * 2048 + off]);
        }
        // .noinc: one expected arrival per thread when its cp.asyncs complete
        asm volatile("cp.async.mbarrier.arrive.noinc.shared::cta.b64 [%0];"
                     :: "r"(sbase + s * 8) : "memory");
    };

    // prologue: fill stages 0..4 with chunks 0..4
    #pragma unroll
    for (int s = 0; s < STAGES - 1; s++)
        load_stage(s, s);

    float acc[2][8][4];
    #pragma unroll
    for (int mt = 0; mt < 2; mt++)
        #pragma unroll
        for (int nt = 0; nt < 8; nt++)
            #pragma unroll
            for (int j = 0; j < 4; j++) acc[mt][nt][j] = 0.0f;

    // A ldmatrix lane-address components (validated mapping)
    int r8 = lane & 7;
    int agrp_row = ((lane >> 3) & 1) * 8;
    int agrp_col = (lane >> 4) * 16;

    // pipeline cursors (explicit wrap, STAGES=6 not a power of 2).
    // p_ephase starts at 1: the wrap after loading stage 5 flips it to 0,
    // matching the consumer's first releases (phase 0) for pf=6..11.
    int p_stage = STAGES - 1, p_ephase = 1;    // producer: next stage, empty-wait parity
    int c_stage = 0, c_phase = 0;              // consumer: stage + full parity

    for (int kc = 0; kc < NCHUNK; kc++) {
        // -------- producer: fill stage for chunk kc+5 --------
        int pf = kc + STAGES - 1;
        if (pf < NCHUNK) {
            if (pf >= STAGES)                  // stage previously used: wait readers
                mbar_wait_parity(sbase + 64 + p_stage * 8, p_ephase);
            load_stage(pf, p_stage);
            if (++p_stage == STAGES) { p_stage = 0; p_ephase ^= 1; }
        }

        // -------- consumer: chunk kc --------
        mbar_wait_parity(sbase + c_stage * 8, c_phase);

        uint32_t sA = sbase + SM_TILES + c_stage * STAGE_BYTES;
        uint32_t sB = sA + A_SM_BYTES;

        #pragma unroll
        for (int ks = 0; ks < 2; ks++) {
            // B: 2 x LDS.128 -> 8 words; word nt -> 2 half2 regs via PRMT
            uint32_t bw[8];
            uint32_t baddr = sB + nbl * 2048 + ks * 1024 + lane * 16;
            lds128(bw[0], bw[1], bw[2], bw[3], baddr);
            lds128(bw[4], bw[5], bw[6], bw[7], baddr + 512);
            uint32_t b[8][2];
            #pragma unroll
            for (int nt = 0; nt < 8; nt++) {
                b[nt][0] = prmt(bw[nt], 0x1404u);   // [00,H(e0),00,H(e1)]
                b[nt][1] = prmt(bw[nt], 0x3424u);
            }
            #pragma unroll
            for (int mt = 0; mt < 2; mt++) {
                int row = wm + mt * 16 + agrp_row + r8;
                uint32_t a[4];
                ldsm_x4(a[0], a[1], a[2], a[3], sA + row * ASTRIDE + ks * 32 + agrp_col);
                #pragma unroll
                for (int nt = 0; nt < 8; nt++)
                    mma16816(acc[mt][nt], a, b[nt]);
            }
        }
        // reads of stage done: release it
        asm volatile("mbarrier.arrive.shared.b64 _, [%0];" :: "r"(sbase + 64 + c_stage * 8) : "memory");
        if (++c_stage == STAGES) { c_stage = 0; c_phase ^= 1; }
    }

    // ---- epilogue: scaled fp32 stores, one 32B sector per lane-quad ----
    float sc = *scale_ptr;
    int g = lane >> 2, t = lane & 3;
    #pragma unroll
    for (int mt = 0; mt < 2; mt++) {
        #pragma unroll
        for (int nt = 0; nt < 8; nt++) {
            int row = m0 + wm + mt * 16 + g;
            int col = n0 + wn + nt * 8 + 2 * t;
            float2 v0 = make_float2(acc[mt][nt][0] * sc, acc[mt][nt][1] * sc);
            float2 v1 = make_float2(acc[mt][nt][2] * sc, acc[mt][nt][3] * sc);
            *(float2*)(out + (size_t)row * N_TOTAL + col) = v0;
            *(float2*)(out + (size_t)(row + 8) * N_TOTAL + col) = v1;
        }
    }
}

// ---------------- launch ----------------
extern "C" void kernel_launch(void* const* d_in, const int* in_sizes, int n_in,
                              void* d_out, int out_size) {
    // identify inputs by element count (robust to ordering)
    const float* x = nullptr;
    const void* kern = nullptr;
    const float* scale = nullptr;
    for (int i = 0; i < n_in; i++) {
        if (in_sizes[i] == M_TOTAL * K_TOTAL) x = (const float*)d_in[i];
        else if (in_sizes[i] == K_TOTAL * N_TOTAL) kern = (const void*)d_in[i];
        else if (in_sizes[i] == 1) scale = (const float*)d_in[i];
    }
    float* out = (float*)d_out;

    cudaFuncSetAttribute(gemm_kernel, cudaFuncAttributeMaxDynamicSharedMemorySize, SMEM_TOTAL);

    // merged prep: 256 pack blocks + 8192 convert blocks
    prep_kernel<<<256 + (M_TOTAL * K_TOTAL) / (256 * 8), 256>>>(x, kern);
    // grid.x = N tiles (adjacent CTAs share the A tile in L2), grid.y = M tiles
    gemm_kernel<<<dim3(N_TOTAL / BN, M_TOTAL / BM), 256, SMEM_TOTAL>>>(scale, out);
}

// round 13
// speedup vs baseline: 1.5265x; 1.0167x over previous
#include <cuda_runtime.h>
#include <cuda_fp16.h>
#include <cstdint>

// out[b,s,f] = scale * x[b,s,:] @ W, W = kernel ? +1 : -1
// GEMM: M=16384, K=1024, N=1024. mma.sync m16n8k16, fp32 accum.
// R13: BK 32 -> 64 (two K-chunks per stage) halves sync/cursor/issue
// overhead per unit of tensor work. STAGES=4 (power of two, proven parity).

#define M_TOTAL 16384
#define N_TOTAL 1024
#define K_TOTAL 1024

#define BM 128
#define BN 128
#define BK 64
#define STAGES 4
#define NCHUNK (K_TOTAL / BK)      // 16
#define ASTRIDE 144                // A smem row: 128B data + 16B pad (conflict-free ldsm)
#define A_SM_BYTES (BM * ASTRIDE)  // 18432
#define B_SM_BYTES 8192            // 2 k-subs x 2 nb-blocks x 2048B fragment bytes
#define STAGE_BYTES (A_SM_BYTES + B_SM_BYTES)   // 26624
#define SM_TILES 1024
#define SMEM_TOTAL (SM_TILES + STAGES * STAGE_BYTES)   // 107520 (x2 CTAs = 215KB <= 228KB)

__device__ __half g_xh[(size_t)M_TOTAL * K_TOTAL];        // 32 MB fp16 activations
__device__ unsigned char g_b8[(size_t)N_TOTAL * K_TOTAL]; // 1 MB fragment-ordered B bytes

// ---------------- helpers ----------------
__device__ __forceinline__ uint32_t smem_u32(const void* p) {
    uint32_t a;
    asm("{ .reg .u64 t; cvta.to.shared.u64 t, %1; cvt.u32.u64 %0, t; }" : "=r"(a) : "l"(p));
    return a;
}
__device__ __forceinline__ void cp_async16(uint32_t dst, const void* src) {
    asm volatile("cp.async.cg.shared.global [%0], [%1], 16;" :: "r"(dst), "l"(src) : "memory");
}
__device__ __forceinline__ void ldsm_x4(uint32_t& r0, uint32_t& r1, uint32_t& r2, uint32_t& r3,
                                        uint32_t addr) {
    asm volatile("ldmatrix.sync.aligned.m8n8.x4.shared.b16 {%0,%1,%2,%3}, [%4];"
                 : "=r"(r0), "=r"(r1), "=r"(r2), "=r"(r3) : "r"(addr));
}
__device__ __forceinline__ void lds128(uint32_t& r0, uint32_t& r1, uint32_t& r2, uint32_t& r3,
                                       uint32_t addr) {
    asm volatile("ld.shared.v4.u32 {%0,%1,%2,%3}, [%4];"
                 : "=r"(r0), "=r"(r1), "=r"(r2), "=r"(r3) : "r"(addr));
}
__device__ __forceinline__ uint32_t prmt(uint32_t a, uint32_t sel) {
    uint32_t d;
    asm("prmt.b32 %0, %1, %2, %3;" : "=r"(d) : "r"(a), "r"(0u), "r"(sel));
    return d;
}
__device__ __forceinline__ void mma16816(float* d, const uint32_t* a, const uint32_t* b) {
    asm volatile(
        "mma.sync.aligned.m16n8k16.row.col.f32.f16.f16.f32 "
        "{%0,%1,%2,%3}, {%4,%5,%6,%7}, {%8,%9}, {%0,%1,%2,%3};"
        : "+f"(d[0]), "+f"(d[1]), "+f"(d[2]), "+f"(d[3])
        : "r"(a[0]), "r"(a[1]), "r"(a[2]), "r"(a[3]), "r"(b[0]), "r"(b[1]));
}
__device__ __forceinline__ void mbar_wait_parity(uint32_t mbar, uint32_t parity) {
    uint32_t done;
    asm volatile(
        "{ .reg .pred p; mbarrier.try_wait.parity.acquire.cta.shared::cta.b64 p, [%1], %2; selp.b32 %0, 1, 0, p; }"
        : "=r"(done) : "r"(mbar), "r"(parity) : "memory");
    if (!done) {
        asm volatile(
            "{ .reg .pred P1;\n"
            "WL_%=: mbarrier.try_wait.parity.acquire.cta.shared::cta.b64 P1, [%0], %1, 0x989680;\n"
            "@P1 bra.uni WD_%=;\n"
            "bra.uni WL_%=;\n"
            "WD_%=: }"
            :: "r"(mbar), "r"(parity) : "memory");
    }
}

// ---------------- merged prep kernel ----------------
// blocks [0,256): pack B bytes (fragment order, dtype auto-detect).
// blocks [256, 256+8192): fp32 -> fp16 convert of x.
__global__ void prep_kernel(const float* __restrict__ x, const void* __restrict__ kern) {
    if (blockIdx.x >= 256) {
        size_t i = (size_t)(blockIdx.x - 256) * blockDim.x + threadIdx.x;  // 8 floats per thread
        size_t base = i * 8;
        float4 a = *(const float4*)(x + base);
        float4 b = *(const float4*)(x + base + 4);
        __half2 h[4];
        h[0] = __floats2half2_rn(a.x, a.y);
        h[1] = __floats2half2_rn(a.z, a.w);
        h[2] = __floats2half2_rn(b.x, b.y);
        h[3] = __floats2half2_rn(b.z, b.w);
        *(uint4*)(&g_xh[base]) = *(uint4*)h;
        return;
    }

    // ---- pack B (with per-block dtype-width detection; L2-cached scan) ----
    __shared__ int notw, noth;
    int t = threadIdx.x;
    if (t == 0) { notw = 0; noth = 0; }
    __syncthreads();
    const uint32_t* kw = (const uint32_t*)kern;
    for (int i = t; i < 1024; i += 256) {
        uint32_t w = kw[i];
        if (!(w == 0u || w == 1u || w == 0x3F800000u)) notw = 1;
        uint32_t h0 = w & 0xFFFFu, h1 = w >> 16;
        if (!((h0 == 0u || h0 == 1u || h0 == 0x3F80u || h0 == 0x3C00u) &&
              (h1 == 0u || h1 == 1u || h1 == 0x3F80u || h1 == 0x3C00u))) noth = 1;
    }
    __syncthreads();
    int width = (!notw) ? 4 : ((!noth) ? 2 : 1);

    int gid = blockIdx.x * 256 + t;        // 65536 groups x 16 bytes
    int lane = gid & 31;
    int q = (gid >> 5) & 1;
    int ks = (gid >> 6) & 1;
    int blk = gid >> 7;                    // k32*16 + nb
    int k32 = blk >> 4;
    int nb = blk & 15;

    unsigned char bytes[16];
    #pragma unroll
    for (int j = 0; j < 16; j++) {
        int nt = q * 4 + (j >> 2);
        int reg = (j >> 1) & 1;
        int e = j & 1;
        int n = nb * 64 + nt * 8 + (lane >> 2);
        int k = k32 * 32 + ks * 16 + reg * 8 + 2 * (lane & 3) + e;
        size_t idx = (size_t)k * N_TOTAL + n;
        bool v = (width == 4) ? (((const uint32_t*)kern)[idx] != 0u)
               : (width == 2) ? (((const uint16_t*)kern)[idx] != 0u)
                              : (((const uint8_t*)kern)[idx] != 0u);
        bytes[j] = v ? 0x3C : 0xBC;        // fp16 high byte of +1 / -1
    }
    *(uint4*)&g_b8[(size_t)gid * 16] = *(uint4*)bytes;
}

// ---------------- GEMM (mma.sync, mbarrier-decoupled, byte-B, BK=64) ----------------
__global__ __launch_bounds__(256, 2)
void gemm_kernel(const float* __restrict__ scale_ptr, float* __restrict__ out) {
    extern __shared__ __align__(16) char smem[];
    uint32_t sbase = smem_u32(smem);
    int tid = threadIdx.x;
    int lane = tid & 31;
    int wid = tid >> 5;

    int n0 = blockIdx.x * BN;
    int m0 = blockIdx.y * BM;
    int nb0 = n0 >> 6;                     // first 64-wide n-block of this CTA

    // warp tile: 32(M) x 64(N); warps laid out 4(M) x 2(N)
    int wm = (wid & 3) * 32;
    int wn = (wid >> 2) * 64;
    int nbl = wn >> 6;                     // 0 or 1: local n-block

    // mbarriers: full[s] at sbase + s*8, empty[s] at sbase + 32 + s*8
    if (tid == 0) {
        #pragma unroll
        for (int s = 0; s < STAGES; s++) {
            asm volatile("mbarrier.init.shared.b64 [%0], %1;" :: "r"(sbase + s * 8), "r"(256) : "memory");
            asm volatile("mbarrier.init.shared.b64 [%0], %1;" :: "r"(sbase + 32 + s * 8), "r"(256) : "memory");
        }
    }
    __syncthreads();

    auto load_stage = [&](int kc, int s) {   // kc in units of BK=64
        uint32_t sA = sbase + SM_TILES + s * STAGE_BYTES;
        uint32_t sB = sA + A_SM_BYTES;
        #pragma unroll
        for (int i = 0; i < 4; i++) {           // A: 1024 x 16B chunks / 256 threads
            int c = tid + i * 256;
            int row = c >> 3, seg = c & 7;
            cp_async16(sA + row * ASTRIDE + seg * 16,
                       &g_xh[(size_t)(m0 + row) * K_TOTAL + kc * BK + seg * 8]);
        }
        #pragma unroll
        for (int i = 0; i < 2; i++) {           // B: 512 x 16B fragment-byte chunks
            int c = tid + i * 256;
            int sub = c >> 8;                   // k32 sub-block 0/1
            int rem = c & 255;
            int nbl_t = rem >> 7;
            int off = (rem & 127) * 16;
            cp_async16(sB + sub * 4096 + nbl_t * 2048 + off,
                       &g_b8[((size_t)((kc * 2 + sub) * 16 + nb0 + nbl_t)) * 2048 + off]);
        }
        // .noinc: one expected arrival per thread when its cp.asyncs complete
        asm volatile("cp.async.mbarrier.arrive.noinc.shared::cta.b64 [%0];"
                     :: "r"(sbase + s * 8) : "memory");
    };

    // prologue: fill stages 0..2 with chunks 0..2
    #pragma unroll
    for (int s = 0; s < STAGES - 1; s++)
        load_stage(s, s);

    float acc[2][8][4];
    #pragma unroll
    for (int mt = 0; mt < 2; mt++)
        #pragma unroll
        for (int nt = 0; nt < 8; nt++)
            #pragma unroll
            for (int j = 0; j < 4; j++) acc[mt][nt][j] = 0.0f;

    // A ldmatrix lane-address components (validated mapping)
    int r8 = lane & 7;
    int agrp_row = ((lane >> 3) & 1) * 8;
    int agrp_col = (lane >> 4) * 16;

    for (int kc = 0; kc < NCHUNK; kc++) {
        // -------- producer: fill stage for chunk kc+3 --------
        int pf = kc + STAGES - 1;
        if (pf < NCHUNK) {
            int ps = pf & (STAGES - 1);
            int rp = pf >> 2;
            if (rp >= 1)
                mbar_wait_parity(sbase + 32 + ps * 8, (rp - 1) & 1);
            load_stage(pf, ps);
        }

        // -------- consumer: chunk kc (4 k16 steps) --------
        int s = kc & (STAGES - 1);
        int r = kc >> 2;
        mbar_wait_parity(sbase + s * 8, r & 1);

        uint32_t sA = sbase + SM_TILES + s * STAGE_BYTES;
        uint32_t sB = sA + A_SM_BYTES;

        #pragma unroll
        for (int ks = 0; ks < 4; ks++) {
            int sub = ks >> 1, ksl = ks & 1;
            // B: 2 x LDS.128 -> 8 words; word nt -> 2 half2 regs via PRMT
            uint32_t bw[8];
            uint32_t baddr = sB + sub * 4096 + nbl * 2048 + ksl * 1024 + lane * 16;
            lds128(bw[0], bw[1], bw[2], bw[3], baddr);
            lds128(bw[4], bw[5], bw[6], bw[7], baddr + 512);
            uint32_t b[8][2];
            #pragma unroll
            for (int nt = 0; nt < 8; nt++) {
                b[nt][0] = prmt(bw[nt], 0x1404u);   // [00,H(e0),00,H(e1)]
                b[nt][1] = prmt(bw[nt], 0x3424u);
            }
            #pragma unroll
            for (int mt = 0; mt < 2; mt++) {
                int row = wm + mt * 16 + agrp_row + r8;
                uint32_t a[4];
                ldsm_x4(a[0], a[1], a[2], a[3], sA + row * ASTRIDE + ks * 32 + agrp_col);
                #pragma unroll
                for (int nt = 0; nt < 8; nt++)
                    mma16816(acc[mt][nt], a, b[nt]);
            }
        }
        // reads of stage done: release it
        asm volatile("mbarrier.arrive.shared.b64 _, [%0];" :: "r"(sbase + 32 + s * 8) : "memory");
    }

    // ---- epilogue: scaled fp32 stores, one 32B sector per lane-quad ----
    float sc = *scale_ptr;
    int g = lane >> 2, t = lane & 3;
    #pragma unroll
    for (int mt = 0; mt < 2; mt++) {
        #pragma unroll
        for (int nt = 0; nt < 8; nt++) {
            int row = m0 + wm + mt * 16 + g;
            int col = n0 + wn + nt * 8 + 2 * t;
            float2 v0 = make_float2(acc[mt][nt][0] * sc, acc[mt][nt][1] * sc);
            float2 v1 = make_float2(acc[mt][nt][2] * sc, acc[mt][nt][3] * sc);
            *(float2*)(out + (size_t)row * N_TOTAL + col) = v0;
            *(float2*)(out + (size_t)(row + 8) * N_TOTAL + col) = v1;
        }
    }
}

// ---------------- launch ----------------
extern "C" void kernel_launch(void* const* d_in, const int* in_sizes, int n_in,
                              void* d_out, int out_size) {
    // identify inputs by element count (robust to ordering)
    const float* x = nullptr;
    const void* kern = nullptr;
    const float* scale = nullptr;
    for (int i = 0; i < n_in; i++) {
        if (in_sizes[i] == M_TOTAL * K_TOTAL) x = (const float*)d_in[i];
        else if (in_sizes[i] == K_TOTAL * N_TOTAL) kern = (const void*)d_in[i];
        else if (in_sizes[i] == 1) scale = (const float*)d_in[i];
    }
    float* out = (float*)d_out;

    cudaFuncSetAttribute(gemm_kernel, cudaFuncAttributeMaxDynamicSharedMemorySize, SMEM_TOTAL);

    // merged prep: 256 pack blocks + 8192 convert blocks
    prep_kernel<<<256 + (M_TOTAL * K_TOTAL) / (256 * 8), 256>>>(x, kern);
    // grid.x = N tiles (adjacent CTAs share the A tile in L2), grid.y = M tiles
    gemm_kernel<<<dim3(N_TOTAL / BN, M_TOTAL / BM), 256, SMEM_TOTAL>>>(scale, out);
}